// round 2
// baseline (speedup 1.0000x reference)
#include <cuda_runtime.h>
#include <cuda_bf16.h>
#include <math.h>

// ---------------------------------------------------------------------------
// MXFP4 activation quantizer.
//   act: (4, 4096, 4096) fp32.  GROUP=32, D=4096 -> 128 group-columns.
//   max_abs reduced over (batch, rows, within-group) -> 128 scales total.
//   exps[g] = floor(log2(max_abs[g])) (0 if max==0); s = 2^exps
//   q = copysign( rint(min(|a|/s,1)*8) * (s/8), a )
// Output: q (N floats) followed by exps (128 floats).
// ---------------------------------------------------------------------------

#define NG 128

__device__ unsigned int g_maxbits[NG];   // abs-max per group, as uint bits
__device__ float        g_inv[NG];       // 1/s   (exact power of 2)
__device__ float        g_s8[NG];        // s/8   (exact power of 2)

// ---- kernel 0: zero the scratch max array (deterministic per-launch init) ----
__global__ void k_init() {
    g_maxbits[threadIdx.x] = 0u;
}

// ---- kernel 1: per-group abs-max reduction over all rows ----
// blockDim = 1024.  One row = 4096 floats = 1024 float4 -> thread t always
// owns column-quad t, so its group g = t>>3 is loop-invariant.
__global__ void __launch_bounds__(1024, 2)
k_max(const float4* __restrict__ act, int n4) {
    __shared__ unsigned int smax[NG];
    const int t = threadIdx.x;
    if (t < NG) smax[t] = 0u;
    __syncthreads();

    const int stride = gridDim.x * 1024;
    int i = blockIdx.x * 1024 + t;

    float m0 = 0.f, m1 = 0.f, m2 = 0.f, m3 = 0.f;
    // 4-way unrolled independent accumulators for MLP
    for (; i + 3 * stride < n4; i += 4 * stride) {
        float4 a = act[i];
        float4 b = act[i + stride];
        float4 c = act[i + 2 * stride];
        float4 d = act[i + 3 * stride];
        m0 = fmaxf(m0, fmaxf(fmaxf(fabsf(a.x), fabsf(a.y)), fmaxf(fabsf(a.z), fabsf(a.w))));
        m1 = fmaxf(m1, fmaxf(fmaxf(fabsf(b.x), fabsf(b.y)), fmaxf(fabsf(b.z), fabsf(b.w))));
        m2 = fmaxf(m2, fmaxf(fmaxf(fabsf(c.x), fabsf(c.y)), fmaxf(fabsf(c.z), fabsf(c.w))));
        m3 = fmaxf(m3, fmaxf(fmaxf(fabsf(d.x), fabsf(d.y)), fmaxf(fabsf(d.z), fabsf(d.w))));
    }
    for (; i < n4; i += stride) {
        float4 a = act[i];
        m0 = fmaxf(m0, fmaxf(fmaxf(fabsf(a.x), fabsf(a.y)), fmaxf(fabsf(a.z), fabsf(a.w))));
    }
    float m = fmaxf(fmaxf(m0, m1), fmaxf(m2, m3));

    // reduce across the 8 lanes sharing this group (lanes differ in bits 0..2)
    #pragma unroll
    for (int off = 1; off < 8; off <<= 1)
        m = fmaxf(m, __shfl_xor_sync(0xffffffffu, m, off));

    if ((t & 7) == 0)
        atomicMax(&smax[t >> 3], __float_as_uint(m));   // m >= 0: uint order == float order
    __syncthreads();
    if (t < NG)
        atomicMax(&g_maxbits[t], smax[t]);
}

// ---- kernel 2: exps + scale tables (128 threads) ----
// Powers of two built by bit manipulation: exact, no MUFU involved.
__global__ void k_scales(float* __restrict__ exps_out) {
    const int g = threadIdx.x;
    const float m = __uint_as_float(g_maxbits[g]);
    int e = (m > 0.f) ? ilogbf(m) : 0;    // exact floor(log2(m)) for normals
    // 2^k as bits: (127+k)<<23, valid while 127+k in [1,254] (e in [-126,124])
    g_inv[g] = __uint_as_float((unsigned)(127 - e)       << 23);  // 2^-e
    g_s8[g]  = __uint_as_float((unsigned)(127 + (e - 3)) << 23);  // 2^(e-3)
    exps_out[g] = (float)e;
}

// ---- kernel 3: elementwise requantize ----
__global__ void __launch_bounds__(1024, 2)
k_quant(const float4* __restrict__ act, float4* __restrict__ out, int n4) {
    const int t = threadIdx.x;
    const int g = t >> 3;                      // loop-invariant group
    const float inv = g_inv[g];
    const float s8  = g_s8[g];

    const int stride = gridDim.x * 1024;
    for (int i = blockIdx.x * 1024 + t; i < n4; i += stride) {
        float4 v = act[i];
        float rx = fminf(fabsf(v.x) * inv, 1.0f);
        float ry = fminf(fabsf(v.y) * inv, 1.0f);
        float rz = fminf(fabsf(v.z) * inv, 1.0f);
        float rw = fminf(fabsf(v.w) * inv, 1.0f);
        v.x = copysignf(rintf(rx * 8.0f) * s8, v.x);
        v.y = copysignf(rintf(ry * 8.0f) * s8, v.y);
        v.z = copysignf(rintf(rz * 8.0f) * s8, v.z);
        v.w = copysignf(rintf(rw * 8.0f) * s8, v.w);
        out[i] = v;
    }
}

extern "C" void kernel_launch(void* const* d_in, const int* in_sizes, int n_in,
                              void* d_out, int out_size) {
    const float* act = (const float*)d_in[0];
    float* out = (float*)d_out;
    const int n  = in_sizes[0];          // 67,108,864
    const int n4 = n >> 2;               // float4 count (16,777,216)
    float* exps_out = out + n;           // exps tail (128 floats)

    const int threads = 1024;
    const int grid1 = 1184;              // 8 waves-ish; grid-stride handles rest
    const int grid2 = 1184;

    k_init<<<1, NG>>>();
    k_max<<<grid1, threads>>>((const float4*)act, n4);
    k_scales<<<1, NG>>>(exps_out);
    k_quant<<<grid2, threads>>>((const float4*)act, (float4*)out, n4);
}

// round 3
// speedup vs baseline: 1.0295x; 1.0295x over previous
#include <cuda_runtime.h>
#include <cuda_bf16.h>
#include <math.h>

// ---------------------------------------------------------------------------
// MXFP4 activation quantizer.
//   act: (4, 4096, 4096) fp32.  GROUP=32, D=4096 -> 128 group-columns.
//   max_abs reduced over (batch, rows, within-group) -> 128 values total.
//   exps[g] = floor(log2(max_abs[g])) (0 if max==0); s = 2^exps
//   q = copysign( rint(min(|a|/s,1)*8) * (s/8), a )
//     = copysign( rint(min(|a|*(8/s), 8)) * (s/8), a )
// Output: q (N floats) followed by exps (128 floats).
// ---------------------------------------------------------------------------

#define NG 128
#define THREADS 1024
#define GRID 2048          // n4 = 16,777,216 = 2048*1024*8 exactly

__device__ unsigned int g_maxbits[NG];   // abs-max per group (uint bits); zeroed by k_scales
__device__ float        g_inv8[NG];      // 8/s  (exact power of 2)
__device__ float        g_s8[NG];        // s/8  (exact power of 2)

// ---- kernel 1: per-group abs-max over all rows ----
// One row = 4096 floats = 1024 float4 -> thread t always owns column-quad t,
// so its group g = t>>3 is loop-invariant.
__global__ void __launch_bounds__(THREADS, 2)
k_max(const float4* __restrict__ act, int n4) {
    __shared__ unsigned int smax[NG];
    const int t = threadIdx.x;
    if (t < NG) smax[t] = 0u;
    __syncthreads();

    const int stride = GRID * THREADS;
    int i = blockIdx.x * THREADS + t;

    float m0 = 0.f, m1 = 0.f, m2 = 0.f, m3 = 0.f;
    // exact trip count: 2 iterations of the 4x body, no tail
    #pragma unroll 2
    for (; i + 3 * stride < n4; i += 4 * stride) {
        float4 a = __ldcs(&act[i]);
        float4 b = __ldcs(&act[i + stride]);
        float4 c = __ldcs(&act[i + 2 * stride]);
        float4 d = __ldcs(&act[i + 3 * stride]);
        m0 = fmaxf(m0, fmaxf(fmaxf(fabsf(a.x), fabsf(a.y)), fmaxf(fabsf(a.z), fabsf(a.w))));
        m1 = fmaxf(m1, fmaxf(fmaxf(fabsf(b.x), fabsf(b.y)), fmaxf(fabsf(b.z), fabsf(b.w))));
        m2 = fmaxf(m2, fmaxf(fmaxf(fabsf(c.x), fabsf(c.y)), fmaxf(fabsf(c.z), fabsf(c.w))));
        m3 = fmaxf(m3, fmaxf(fmaxf(fabsf(d.x), fabsf(d.y)), fmaxf(fabsf(d.z), fabsf(d.w))));
    }
    for (; i < n4; i += stride) {   // generic tail (not taken at this size)
        float4 a = __ldcs(&act[i]);
        m0 = fmaxf(m0, fmaxf(fmaxf(fabsf(a.x), fabsf(a.y)), fmaxf(fabsf(a.z), fabsf(a.w))));
    }
    float m = fmaxf(fmaxf(m0, m1), fmaxf(m2, m3));

    // reduce across the 8 lanes sharing this group (lanes differ in bits 0..2)
    #pragma unroll
    for (int off = 1; off < 8; off <<= 1)
        m = fmaxf(m, __shfl_xor_sync(0xffffffffu, m, off));

    if ((t & 7) == 0)
        atomicMax(&smax[t >> 3], __float_as_uint(m));   // m >= 0: uint order == float order
    __syncthreads();
    if (t < NG)
        atomicMax(&g_maxbits[t], smax[t]);
}

// ---- kernel 2: exps + scale tables (128 threads), then self-clear scratch ----
// Powers of two built by bit manipulation: exact, no MUFU.
__global__ void k_scales(float* __restrict__ exps_out) {
    const int g = threadIdx.x;
    const float m = __uint_as_float(g_maxbits[g]);
    int e = (m > 0.f) ? ilogbf(m) : 0;    // exact floor(log2(m)) for normals
    // 2^k bits: (127+k)<<23, valid for 127+k in [1,254]
    g_inv8[g] = __uint_as_float((unsigned)(127 + (3 - e)) << 23);  // 2^(3-e) = 8/s
    g_s8[g]   = __uint_as_float((unsigned)(127 + (e - 3)) << 23);  // 2^(e-3) = s/8
    exps_out[g] = (float)e;
    g_maxbits[g] = 0u;   // leave state as found: next launch needs zeros
}

// ---- kernel 3: elementwise requantize ----
__global__ void __launch_bounds__(THREADS, 2)
k_quant(const float4* __restrict__ act, float4* __restrict__ out, int n4) {
    const int t = threadIdx.x;
    const int g = t >> 3;                      // loop-invariant group
    const float inv8 = g_inv8[g];
    const float s8   = g_s8[g];

    const int stride = GRID * THREADS;
    int i = blockIdx.x * THREADS + t;
    #pragma unroll 4
    for (; i < n4; i += stride) {              // exactly 8 trips
        float4 v = __ldcs(&act[i]);
        float rx = fminf(fabsf(v.x) * inv8, 8.0f);
        float ry = fminf(fabsf(v.y) * inv8, 8.0f);
        float rz = fminf(fabsf(v.z) * inv8, 8.0f);
        float rw = fminf(fabsf(v.w) * inv8, 8.0f);
        v.x = copysignf(rintf(rx) * s8, v.x);
        v.y = copysignf(rintf(ry) * s8, v.y);
        v.z = copysignf(rintf(rz) * s8, v.z);
        v.w = copysignf(rintf(rw) * s8, v.w);
        __stcs(&out[i], v);
    }
}

extern "C" void kernel_launch(void* const* d_in, const int* in_sizes, int n_in,
                              void* d_out, int out_size) {
    const float* act = (const float*)d_in[0];
    float* out = (float*)d_out;
    const int n  = in_sizes[0];          // 67,108,864
    const int n4 = n >> 2;               // 16,777,216 float4
    float* exps_out = out + n;           // exps tail (128 floats)

    k_max<<<GRID, THREADS>>>((const float4*)act, n4);
    k_scales<<<1, NG>>>(exps_out);
    k_quant<<<GRID, THREADS>>>((const float4*)act, (float4*)out, n4);
}

// round 5
// speedup vs baseline: 1.0635x; 1.0330x over previous
#include <cuda_runtime.h>
#include <cuda_bf16.h>
#include <math.h>

// ---------------------------------------------------------------------------
// MXFP4 activation quantizer.
//   act: (4, 4096, 4096) fp32.  GROUP=32, D=4096 -> 128 group-columns.
//   max_abs reduced over (batch, rows, within-group) -> 128 values total.
//   exps[g] = floor(log2(max_abs[g])) (0 if max==0); s = 2^exps
//   q = copysign( rint(min(|a|*(8/s), 8)) * (s/8), a )
// Output: q (N floats) followed by exps (128 floats).
//
// Traffic plan: k_max reads act with evict-normal so its final ~120MB of
// reads (upper half of the array) stay resident in L2 across the launch
// boundary; k_quant walks the array in REVERSE so it consumes those lines
// from L2 first. Stores are evict-first to protect the resident act lines.
// ---------------------------------------------------------------------------

#define NG 128
#define THREADS 1024
#define GRID 2048          // n4 = 16,777,216 = 2048*1024*8 exactly

__device__ unsigned int g_maxbits[NG];   // abs-max per group (uint bits); zeroed by k_scales
__device__ float        g_inv8[NG];      // 8/s  (exact power of 2)
__device__ float        g_s8[NG];        // s/8  (exact power of 2)

// ---- kernel 1: per-group abs-max over all rows ----
// One row = 4096 floats = 1024 float4 -> thread t always owns column-quad t,
// so its group g = t>>3 is loop-invariant.
__global__ void __launch_bounds__(THREADS, 2)
k_max(const float4* __restrict__ act, int n4) {
    __shared__ unsigned int smax[NG];
    const int t = threadIdx.x;
    if (t < NG) smax[t] = 0u;
    __syncthreads();

    const int stride = GRID * THREADS;
    int i = blockIdx.x * THREADS + t;

    float m0 = 0.f, m1 = 0.f, m2 = 0.f, m3 = 0.f;
    // default (evict-normal) loads: the final batch stays resident in L2
    #pragma unroll 2
    for (; i + 3 * stride < n4; i += 4 * stride) {
        float4 a = act[i];
        float4 b = act[i + stride];
        float4 c = act[i + 2 * stride];
        float4 d = act[i + 3 * stride];
        m0 = fmaxf(m0, fmaxf(fmaxf(fabsf(a.x), fabsf(a.y)), fmaxf(fabsf(a.z), fabsf(a.w))));
        m1 = fmaxf(m1, fmaxf(fmaxf(fabsf(b.x), fabsf(b.y)), fmaxf(fabsf(b.z), fabsf(b.w))));
        m2 = fmaxf(m2, fmaxf(fmaxf(fabsf(c.x), fabsf(c.y)), fmaxf(fabsf(c.z), fabsf(c.w))));
        m3 = fmaxf(m3, fmaxf(fmaxf(fabsf(d.x), fabsf(d.y)), fmaxf(fabsf(d.z), fabsf(d.w))));
    }
    for (; i < n4; i += stride) {   // generic tail (not taken at this size)
        float4 a = act[i];
        m0 = fmaxf(m0, fmaxf(fmaxf(fabsf(a.x), fabsf(a.y)), fmaxf(fabsf(a.z), fabsf(a.w))));
    }
    float m = fmaxf(fmaxf(m0, m1), fmaxf(m2, m3));

    // reduce across the 8 lanes sharing this group (lanes differ in bits 0..2)
    #pragma unroll
    for (int off = 1; off < 8; off <<= 1)
        m = fmaxf(m, __shfl_xor_sync(0xffffffffu, m, off));

    if ((t & 7) == 0)
        atomicMax(&smax[t >> 3], __float_as_uint(m));   // m >= 0: uint order == float order
    __syncthreads();
    if (t < NG)
        atomicMax(&g_maxbits[t], smax[t]);
}

// ---- kernel 2: exps + scale tables (128 threads), then self-clear scratch ----
__global__ void k_scales(float* __restrict__ exps_out) {
    const int g = threadIdx.x;
    const float m = __uint_as_float(g_maxbits[g]);
    int e = (m > 0.f) ? ilogbf(m) : 0;    // exact floor(log2(m)) for normals
    // 2^k bits: (127+k)<<23, valid for 127+k in [1,254]
    g_inv8[g] = __uint_as_float((unsigned)(127 + (3 - e)) << 23);  // 2^(3-e) = 8/s
    g_s8[g]   = __uint_as_float((unsigned)(127 + (e - 3)) << 23);  // 2^(e-3) = s/8
    exps_out[g] = (float)e;
    g_maxbits[g] = 0u;   // leave state as found for the next (graph-replayed) launch
}

// ---- kernel 3: elementwise requantize, REVERSED traversal for L2 reuse ----
__global__ void __launch_bounds__(THREADS, 2)
k_quant(const float4* __restrict__ act, float4* __restrict__ out, int n4) {
    const int t = threadIdx.x;
    const int g = t >> 3;                      // loop-invariant group
    const float inv8 = g_inv8[g];
    const float s8   = g_s8[g];

    const int stride  = GRID * THREADS;
    const int b       = (int)gridDim.x - 1 - (int)blockIdx.x;  // reversed block
    const int base    = b * THREADS + t;
    const int nchunks = n4 / stride;           // 8 at this size

    // generic remainder (not taken at this size), done first — order is free
    {
        int r = nchunks * stride + base;
        if (r < n4) {
            float4 v = act[r];
            float rx = fminf(fabsf(v.x) * inv8, 8.0f);
            float ry = fminf(fabsf(v.y) * inv8, 8.0f);
            float rz = fminf(fabsf(v.z) * inv8, 8.0f);
            float rw = fminf(fabsf(v.w) * inv8, 8.0f);
            v.x = copysignf(rintf(rx) * s8, v.x);
            v.y = copysignf(rintf(ry) * s8, v.y);
            v.z = copysignf(rintf(rz) * s8, v.z);
            v.w = copysignf(rintf(rw) * s8, v.w);
            __stcs(&out[r], v);
        }
    }

    // reversed chunk order: highest addresses (freshest in L2) first.
    // __ldlu (last-use): consumed lines release their L2/L1 ways promptly.
    #pragma unroll 4
    for (int k = nchunks - 1; k >= 0; --k) {
        const int i = base + k * stride;
        float4 v = __ldlu(&act[i]);
        float rx = fminf(fabsf(v.x) * inv8, 8.0f);
        float ry = fminf(fabsf(v.y) * inv8, 8.0f);
        float rz = fminf(fabsf(v.z) * inv8, 8.0f);
        float rw = fminf(fabsf(v.w) * inv8, 8.0f);
        v.x = copysignf(rintf(rx) * s8, v.x);
        v.y = copysignf(rintf(ry) * s8, v.y);
        v.z = copysignf(rintf(rz) * s8, v.z);
        v.w = copysignf(rintf(rw) * s8, v.w);
        __stcs(&out[i], v);
    }
}

extern "C" void kernel_launch(void* const* d_in, const int* in_sizes, int n_in,
                              void* d_out, int out_size) {
    const float* act = (const float*)d_in[0];
    float* out = (float*)d_out;
    const int n  = in_sizes[0];          // 67,108,864
    const int n4 = n >> 2;               // 16,777,216 float4
    float* exps_out = out + n;           // exps tail (128 floats)

    k_max<<<GRID, THREADS>>>((const float4*)act, n4);
    k_scales<<<1, NG>>>(exps_out);
    k_quant<<<GRID, THREADS>>>((const float4*)act, (float4*)out, n4);
}